// round 9
// baseline (speedup 1.0000x reference)
#include <cuda_runtime.h>
#include <cuda_bf16.h>

#define BATCH 1024
#define SEQ   256
#define HALF  128

typedef unsigned long long u64;

__device__ __forceinline__ u64 pack2(float lo, float hi) {
    u64 r; asm("mov.b64 %0, {%1,%2};" : "=l"(r) : "f"(lo), "f"(hi)); return r;
}
__device__ __forceinline__ void unpack2(u64 v, float& lo, float& hi) {
    asm("mov.b64 {%0,%1}, %2;" : "=f"(lo), "=f"(hi) : "l"(v));
}
__device__ __forceinline__ u64 ffma2(u64 a, u64 b, u64 c) {
    u64 d; asm("fma.rn.f32x2 %0, %1, %2, %3;" : "=l"(d) : "l"(a), "l"(b), "l"(c)); return d;
}
__device__ __forceinline__ u64 fmul2(u64 a, u64 b) {
    u64 d; asm("mul.rn.f32x2 %0, %1, %2;" : "=l"(d) : "l"(a), "l"(b)); return d;
}
__device__ __forceinline__ float ex2f(float x) {
    float r; asm("ex2.approx.f32 %0, %1;" : "=f"(r) : "f"(x)); return r;
}

// One CTA per batch, 128 threads, 2 query rows per thread.
// CROSS-T f32x2 packing: K/V stored transposed in SMEM as (val[2t], val[2t+1])
// pairs (K pre-scaled by 0.5*log2e). The dot product accumulates a PAIR of
// scores per chain (no horizontal add), EX2 each half, then pair-FMA into
// even/odd accumulators. 9 FMA-pipe instrs per t-step for 2 rows (was 12),
// identical LDS traffic (2x LDS.128 per t for both rows).
__global__ __launch_bounds__(HALF, 6) void hybrid_attn_kernel(
    const float* __restrict__ x,
    const float* __restrict__ Wq, const float* __restrict__ Wk, const float* __restrict__ Wv,
    const float* __restrict__ W1, const float* __restrict__ b1,
    const float* __restrict__ W2, const float* __restrict__ b2,
    const float* __restrict__ W3, const float* __restrict__ b3,
    float* __restrict__ out)
{
    // skA[t2] = ((k0[2t2],k0[2t2+1]), (k1 pair))  [pre-scaled by cs]
    // skB[t2] = ((k2 pair), (k3 pair))
    __shared__ ulonglong2 skA[HALF], skB[HALF];
    __shared__ ulonglong2 svA[HALF], svB[HALF];
    __shared__ float sWq[16], sWk[16], sWv[16];
    __shared__ float sW1[32], sb1[8], sW2[32], sb2[4], sW3[4], sb3;

    const int tid = threadIdx.x;
    const int b   = blockIdx.x;

    if (tid < 16) { sWq[tid] = Wq[tid]; sWk[tid] = Wk[tid]; sWv[tid] = Wv[tid]; }
    if (tid < 32) { sW1[tid] = W1[tid]; sW2[tid] = W2[tid]; }
    if (tid < 8)  { sb1[tid] = b1[tid]; }
    if (tid < 4)  { sb2[tid] = b2[tid]; sW3[tid] = W3[tid]; }
    if (tid == 0) { sb3 = b3[0]; }

    const float4 xa = reinterpret_cast<const float4*>(x)[b * SEQ + tid];
    const float4 xb = reinterpret_cast<const float4*>(x)[b * SEQ + tid + HALF];

    __syncthreads();   // weights staged before any read

    #define PROJ(W, xv, o0, o1, o2, o3)                                        \
        o0 = xv.x*W[0] + xv.y*W[4] + xv.z*W[8]  + xv.w*W[12];                  \
        o1 = xv.x*W[1] + xv.y*W[5] + xv.z*W[9]  + xv.w*W[13];                  \
        o2 = xv.x*W[2] + xv.y*W[6] + xv.z*W[10] + xv.w*W[14];                  \
        o3 = xv.x*W[3] + xv.y*W[7] + xv.z*W[11] + xv.w*W[15];

    const float cs = 0.72134752044448170368f;   // 0.5 * log2(e), folded into K

    float qa0,qa1,qa2,qa3, qb0,qb1,qb2,qb3;
    float t0,t1,t2,t3;

    PROJ(sWq, xa, qa0,qa1,qa2,qa3)
    PROJ(sWq, xb, qb0,qb1,qb2,qb3)

    // Transposed scatter of K,V (scalar STS; one-time, ~2-way bank conflicts).
    float* skAf = reinterpret_cast<float*>(skA);
    float* skBf = reinterpret_cast<float*>(skB);
    float* svAf = reinterpret_cast<float*>(svA);
    float* svBf = reinterpret_cast<float*>(svB);

    #define SCATTER(row)                                                       \
    {   const int i0 = ((row) >> 1) * 4 + ((row) & 1);                         \
        skAf[i0]     = t0 * cs;  skAf[i0 + 2] = t1 * cs;                       \
        skBf[i0]     = t2 * cs;  skBf[i0 + 2] = t3 * cs;  }
    #define SCATTERV(row)                                                      \
    {   const int i0 = ((row) >> 1) * 4 + ((row) & 1);                         \
        svAf[i0]     = t0;       svAf[i0 + 2] = t1;                            \
        svBf[i0]     = t2;       svBf[i0 + 2] = t3;  }

    PROJ(sWk, xa, t0,t1,t2,t3)  SCATTER(tid)
    PROJ(sWk, xb, t0,t1,t2,t3)  SCATTER(tid + HALF)
    PROJ(sWv, xa, t0,t1,t2,t3)  SCATTERV(tid)
    PROJ(sWv, xb, t0,t1,t2,t3)  SCATTERV(tid + HALF)
    #undef PROJ
    #undef SCATTER
    #undef SCATTERV

    // Duplicated q pairs for the cross-t dot.
    const u64 qa0d = pack2(qa0, qa0), qa1d = pack2(qa1, qa1);
    const u64 qa2d = pack2(qa2, qa2), qa3d = pack2(qa3, qa3);
    const u64 qb0d = pack2(qb0, qb0), qb1d = pack2(qb1, qb1);
    const u64 qb2d = pack2(qb2, qb2), qb3d = pack2(qb3, qb3);
    const u64 ONE2 = pack2(1.0f, 1.0f);

    __syncthreads();

    // Even/odd pair accumulators per row: (sum over even t, sum over odd t).
    u64 aA0 = 0, aA1 = 0, aA2 = 0, aA3 = 0, aAL = 0;
    u64 aB0 = 0, aB1 = 0, aB2 = 0, aB3 = 0, aBL = 0;

    #pragma unroll 4
    for (int tt = 0; tt < HALF; ++tt) {
        const ulonglong2 kkA = skA[tt];   // (k0 pair, k1 pair)
        const ulonglong2 kkB = skB[tt];   // (k2 pair, k3 pair)
        const ulonglong2 vvA = svA[tt];   // (v0 pair, v1 pair)
        const ulonglong2 vvB = svB[tt];   // (v2 pair, v3 pair)

        // row A: score pair (s_2t, s_2t+1) — no horizontal add
        u64 sA = ffma2(qa1d, kkA.y, fmul2(qa0d, kkA.x));
        sA = ffma2(qa2d, kkB.x, sA);
        sA = ffma2(qa3d, kkB.y, sA);
        float sA0, sA1; unpack2(sA, sA0, sA1);
        const u64 eA = pack2(ex2f(sA0), ex2f(sA1));

        // row B
        u64 sB = ffma2(qb1d, kkA.y, fmul2(qb0d, kkA.x));
        sB = ffma2(qb2d, kkB.x, sB);
        sB = ffma2(qb3d, kkB.y, sB);
        float sB0, sB1; unpack2(sB, sB0, sB1);
        const u64 eB = pack2(ex2f(sB0), ex2f(sB1));

        aA0 = ffma2(eA, vvA.x, aA0);
        aA1 = ffma2(eA, vvA.y, aA1);
        aA2 = ffma2(eA, vvB.x, aA2);
        aA3 = ffma2(eA, vvB.y, aA3);
        aAL = ffma2(eA, ONE2, aAL);

        aB0 = ffma2(eB, vvA.x, aB0);
        aB1 = ffma2(eB, vvA.y, aB1);
        aB2 = ffma2(eB, vvB.x, aB2);
        aB3 = ffma2(eB, vvB.y, aB3);
        aBL = ffma2(eB, ONE2, aBL);
    }

    // MLP head per row: 4 -> 8 (tanh) -> 4 (tanh) -> 1
    #pragma unroll
    for (int r = 0; r < 2; ++r) {
        float a0, a1, a2, a3, l, lo, hi;
        if (r == 0) {
            unpack2(aA0, lo, hi); a0 = lo + hi;
            unpack2(aA1, lo, hi); a1 = lo + hi;
            unpack2(aA2, lo, hi); a2 = lo + hi;
            unpack2(aA3, lo, hi); a3 = lo + hi;
            unpack2(aAL, lo, hi); l  = lo + hi;
        } else {
            unpack2(aB0, lo, hi); a0 = lo + hi;
            unpack2(aB1, lo, hi); a1 = lo + hi;
            unpack2(aB2, lo, hi); a2 = lo + hi;
            unpack2(aB3, lo, hi); a3 = lo + hi;
            unpack2(aBL, lo, hi); l  = lo + hi;
        }
        const float inv = 1.0f / l;
        a0 *= inv; a1 *= inv; a2 *= inv; a3 *= inv;

        float h1[8];
        #pragma unroll
        for (int i = 0; i < 8; ++i) {
            float u = a0*sW1[0*8+i] + a1*sW1[1*8+i] + a2*sW1[2*8+i] + a3*sW1[3*8+i] + sb1[i];
            h1[i] = tanhf(u);
        }
        float h2[4];
        #pragma unroll
        for (int i = 0; i < 4; ++i) {
            float u = sb2[i];
            #pragma unroll
            for (int j = 0; j < 8; ++j) u += h1[j] * sW2[j*4+i];
            h2[i] = tanhf(u);
        }
        float o = h2[0]*sW3[0] + h2[1]*sW3[1] + h2[2]*sW3[2] + h2[3]*sW3[3] + sb3;
        out[b * SEQ + tid + r * HALF] = o;
    }
}

extern "C" void kernel_launch(void* const* d_in, const int* in_sizes, int n_in,
                              void* d_out, int out_size) {
    const float* x  = (const float*)d_in[0];
    const float* Wq = (const float*)d_in[1];
    const float* Wk = (const float*)d_in[2];
    const float* Wv = (const float*)d_in[3];
    const float* W1 = (const float*)d_in[4];
    const float* b1 = (const float*)d_in[5];
    const float* W2 = (const float*)d_in[6];
    const float* b2 = (const float*)d_in[7];
    const float* W3 = (const float*)d_in[8];
    const float* b3 = (const float*)d_in[9];
    float* out = (float*)d_out;

    hybrid_attn_kernel<<<BATCH, HALF>>>(x, Wq, Wk, Wv, W1, b1, W2, b2, W3, b3, out);
}